// round 1
// baseline (speedup 1.0000x reference)
#include <cuda_runtime.h>

typedef unsigned long long ull;

// Packed fp32x2 FMA (Blackwell): d = a*b + c elementwise on 2 floats.
__device__ __forceinline__ ull ffma2(ull a, ull b, ull c) {
    ull d;
    asm("fma.rn.f32x2 %0, %1, %2, %3;" : "=l"(d) : "l"(a), "l"(b), "l"(c));
    return d;
}

// LocallyConnected2d: B=16, C=32, O=32, 64x64, 3x3, pad 1, stride 1.
// out[b,o,h,w] = sum_{c,kh,kw} x[b,c,h-1+kh,w-1+kw] * w[o,c,h,w,kh*3+kw]
//
// Block = 8 horizontally-adjacent pixels (one oh row segment), 256 threads.
// Warp = one pixel; warp does the full 16b x 32o GEMM over K = 32c*9k.
// Thread tile = 4b x 4o, f32x2-paired over (c even, c odd).
// Weight is streamed from HBM exactly once (all 16 b live in one thread's acc).

__global__ __launch_bounds__(256, 3)
void lc2d_kernel(const float* __restrict__ xin,
                 const float* __restrict__ wgt,
                 float* __restrict__ out)
{
    // w_s: 72 pk-rows x 64 floats ([pk][o-chunk swizzled][o&3][cc]) = 4608
    // x_s: 3 rows x 10 cols x 16 b x 2 cc                           =  960
    __shared__ __align__(16) float smem[5568];
    float* w_s = smem;
    float* x_s = smem + 4608;

    const int tid  = threadIdx.x;
    const int px   = tid >> 5;     // warp id = pixel within tile (0..7)
    const int lane = tid & 31;
    const int bg   = lane & 3;     // batch group: b in [bg*4, bg*4+4)
    const int og   = lane >> 2;    // out-ch group: o in [og*4, og*4+4)

    const int oh      = blockIdx.y;
    const int ow0     = blockIdx.x << 3;
    const int pixbase = oh * 64 + ow0;

    // Per-k SMEM read offsets for weights (pk = px*9+k fixed across c-loop).
    // Swizzle slot = og ^ ((pk + pk>>2)&7) -- spreads STS banks, keeps 32B
    // read chunks intact (LDS.128-aligned).
    int woffk[9];
#pragma unroll
    for (int k = 0; k < 9; ++k) {
        int pk = px * 9 + k;
        int s  = (pk + (pk >> 2)) & 7;
        woffk[k] = (pk << 6) + ((og ^ s) << 3);
    }
    const int xrow = (px << 5) + (bg << 3);  // x_s float offset for this thread

    ull acc[4][4];
#pragma unroll
    for (int i = 0; i < 4; ++i)
#pragma unroll
        for (int j = 0; j < 4; ++j) acc[i][j] = 0ull;

    for (int cc2 = 0; cc2 < 16; ++cc2) {
        const int c = cc2 << 1;
        __syncthreads();  // previous iteration's readers done

        // ---- stage x tile: x_s[row(3)][col(10)][b(16)][cc(2)] ----
#pragma unroll
        for (int ii = 0; ii < 4; ++ii) {
            int i = tid + (ii << 8);
            if (i < 960) {
                int col = i % 10;
                int r   = i / 10;
                int row = r % 3;
                int r3  = r / 3;
                int b   = r3 & 15;
                int ccx = r3 >> 4;
                int ih = oh - 1 + row;
                int iw = ow0 - 1 + col;
                float v = 0.0f;
                if ((unsigned)ih < 64u && (unsigned)iw < 64u)
                    v = xin[((b * 32 + c + ccx) * 64 + ih) * 64 + iw];
                x_s[((row * 10 + col) << 5) + (b << 1) + ccx] = v;
            }
        }

        // ---- stage w: coalesced float4 reads of 72-float (8px x 9k) runs,
        //      scattered into [pk][slot^swz][o&3][cc] ----
#pragma unroll
        for (int ii = 0; ii < 5; ++ii) {
            int f = tid + (ii << 8);
            if (f < 1152) {
                int v4  = f % 18;        // float4 index within run
                int ocw = f / 18;        // 0..63 = (cc,o)
                int o   = ocw & 31;
                int ccw = ocw >> 5;
                const float4 w4 = *reinterpret_cast<const float4*>(
                    wgt + ((o * 32 + c + ccw) * 4096 + pixbase) * 9 + (v4 << 2));
                const float* w4p = reinterpret_cast<const float*>(&w4);
#pragma unroll
                for (int e = 0; e < 4; ++e) {
                    int pk = (v4 << 2) + e;   // = px*9 + k
                    int s  = (pk + (pk >> 2)) & 7;
                    w_s[(pk << 6) + ((((o >> 2) ^ s) << 3)) + ((o & 3) << 1) + ccw]
                        = w4p[e];
                }
            }
        }
        __syncthreads();

        // ---- compute: 9 k-steps, 16 FFMA2 each ----
#pragma unroll
        for (int k = 0; k < 9; ++k) {
            const int kh = k / 3, kw = k % 3;
            const float* xb = x_s + ((kh * 10 + kw) << 5) + xrow;
            ulonglong2 xa = *reinterpret_cast<const ulonglong2*>(xb);
            ulonglong2 xc = *reinterpret_cast<const ulonglong2*>(xb + 4);
            const float* wb = w_s + woffk[k];
            ulonglong2 wa = *reinterpret_cast<const ulonglong2*>(wb);
            ulonglong2 wc = *reinterpret_cast<const ulonglong2*>(wb + 4);
            ull xs2[4] = {xa.x, xa.y, xc.x, xc.y};   // b = bg*4 + 0..3 (c pair)
            ull ws2[4] = {wa.x, wa.y, wc.x, wc.y};   // o = og*4 + 0..3 (c pair)
#pragma unroll
            for (int bi = 0; bi < 4; ++bi)
#pragma unroll
                for (int oi = 0; oi < 4; ++oi)
                    acc[bi][oi] = ffma2(xs2[bi], ws2[oi], acc[bi][oi]);
        }
    }

    // ---- epilogue: reduce c-pair lanes, transpose via SMEM, coalesced STG ----
    __syncthreads();  // done reading w_s/x_s; reuse smem[0..5119]
#pragma unroll
    for (int bi = 0; bi < 4; ++bi)
#pragma unroll
        for (int oi = 0; oi < 4; ++oi) {
            union { ull u; float2 f; } cv;
            cv.u = acc[bi][oi];
            int bo = (((bg << 2) + bi) << 5) + (og << 2) + oi;  // b*32 + o
            smem[bo * 10 + px] = cv.f.x + cv.f.y;
        }
    __syncthreads();
#pragma unroll
    for (int rr = 0; rr < 2; ++rr) {
        int r = tid + (rr << 8);            // r = b*32 + o, 0..511
        const float* sp = smem + r * 10;
        float4 lo = make_float4(sp[0], sp[1], sp[2], sp[3]);
        float4 hi = make_float4(sp[4], sp[5], sp[6], sp[7]);
        float* op = out + (size_t)r * 4096 + pixbase;
        *reinterpret_cast<float4*>(op)     = lo;   // 32B-aligned (ow0 % 8 == 0)
        *reinterpret_cast<float4*>(op + 4) = hi;
    }
}

extern "C" void kernel_launch(void* const* d_in, const int* in_sizes, int n_in,
                              void* d_out, int out_size) {
    const float* x = (const float*)d_in[0];   // [16,32,64,64] f32
    const float* w = (const float*)d_in[1];   // [32,32,64,64,9] f32
    float* out = (float*)d_out;               // [16,32,64,64] f32
    dim3 grid(8, 64);                         // 8 ow-tiles x 64 oh rows
    lc2d_kernel<<<grid, 256>>>(x, w, out);
}

// round 3
// speedup vs baseline: 1.4726x; 1.4726x over previous
#include <cuda_runtime.h>

typedef unsigned long long ull;

// Packed fp32x2 FMA (Blackwell): d = a*b + c elementwise on 2 floats.
__device__ __forceinline__ ull ffma2(ull a, ull b, ull c) {
    ull d;
    asm("fma.rn.f32x2 %0, %1, %2, %3;" : "=l"(d) : "l"(a), "l"(b), "l"(c));
    return d;
}

// LocallyConnected2d: B=16, C=32, O=32, 64x64, 3x3, pad 1, stride 1.
// out[b,o,h,w] = sum_{c,kh,kw} x[b,c,h-1+kh,w-1+kw] * w[o,c,h,w,kh*3+kw]
//
// Block = 8 horizontally-adjacent pixels, 256 threads; warp = one pixel
// doing the full 16b x 32o GEMM over K = 32c*9k; thread tile 4b x 4o,
// f32x2-paired over (c even, c odd).
//
// 2-deep software pipeline: double-buffered smem, gmem->reg prefetch 2
// c-pairs ahead, reg->smem scatter for i+1 issued before compute of i,
// ONE syncthreads per iteration.

__global__ __launch_bounds__(256, 2)
void lc2d_kernel(const float* __restrict__ xin,
                 const float* __restrict__ wgt,
                 float* __restrict__ out)
{
    // [2][4608] weights + [2][960] x, contiguous so epilogue can reuse.
    __shared__ __align__(16) float smem[11136];
    float* w_sA = smem;          // buf*4608 + [pk(72)][slot^swz(8)][o&3(4)][cc(2)]
    float* x_sA = smem + 9216;   // buf*960  + [row3][col10][b16][cc2]

    const int tid  = threadIdx.x;
    const int px   = tid >> 5;
    const int lane = tid & 31;
    const int bg   = lane & 3;
    const int og   = lane >> 2;

    const int oh      = blockIdx.y;
    const int ow0     = blockIdx.x << 3;
    const int pixbase = oh * 64 + ow0;

    // ---- per-thread staging invariants: weights (5 float4 slots) ----
    int wbase[5], wpk0[5], woq[5], wsb[5];
#pragma unroll
    for (int ii = 0; ii < 5; ++ii) {
        int f   = tid + (ii << 8);          // 0..1279 ; valid if < 1152
        int v4  = f % 18;
        int ocw = f / 18;
        int o   = ocw & 31;
        int ccw = ocw >> 5;
        wbase[ii] = ((o * 32 + ccw) * 4096 + pixbase) * 9 + (v4 << 2);
        wpk0[ii]  = v4 << 2;
        woq[ii]   = o >> 2;
        wsb[ii]   = ((o & 3) << 1) + ccw;
    }
    const bool w4ok = (tid < 128);          // slot ii=4 validity (f<1152)

    // ---- x staging invariants (4 scalar slots) ----
    int xbase[4], xso[4];
#pragma unroll
    for (int ii = 0; ii < 4; ++ii) {
        int i = tid + (ii << 8);
        xbase[ii] = -1; xso[ii] = -1;
        if (i < 960) {
            int col = i % 10, r = i / 10;
            int row = r % 3,  r3 = r / 3;
            int b   = r3 & 15, ccx = r3 >> 4;
            int ih = oh - 1 + row, iw = ow0 - 1 + col;
            xso[ii] = ((row * 10 + col) << 5) + (b << 1) + ccx;
            if ((unsigned)ih < 64u && (unsigned)iw < 64u)
                xbase[ii] = (b * 32 + ccx) * 4096 + ih * 64 + iw;
        }
    }

    // per-k weight read offsets (swizzled) and x read row
    int woffk[9];
#pragma unroll
    for (int k = 0; k < 9; ++k) {
        int pk = px * 9 + k;
        int s  = (pk + (pk >> 2)) & 7;
        woffk[k] = (pk << 6) + ((og ^ s) << 3);
    }
    const int xrow = (px << 5) + (bg << 3);

    ull acc[4][4];
#pragma unroll
    for (int i = 0; i < 4; ++i)
#pragma unroll
        for (int j = 0; j < 4; ++j) acc[i][j] = 0ull;

    float4 wr[5];
    float  xr[4];

    // gmem -> regs for c-pair cc2 (c = 2*cc2): advance = c*36864 (w), c*4096 (x)
#define LOADS(CC2)                                                            \
    do {                                                                      \
        int c_ = (CC2) << 1;                                                  \
        _Pragma("unroll")                                                     \
        for (int ii = 0; ii < 4; ++ii)                                        \
            wr[ii] = *reinterpret_cast<const float4*>(                        \
                wgt + wbase[ii] + c_ * 36864);                                \
        if (w4ok)                                                             \
            wr[4] = *reinterpret_cast<const float4*>(                         \
                wgt + wbase[4] + c_ * 36864);                                 \
        _Pragma("unroll")                                                     \
        for (int ii = 0; ii < 4; ++ii)                                        \
            if (xso[ii] >= 0)                                                 \
                xr[ii] = (xbase[ii] >= 0) ? __ldg(xin + xbase[ii] + c_ * 4096)\
                                          : 0.0f;                             \
    } while (0)

    // regs -> smem scatter into buffer BUF
#define STAGE(BUF)                                                            \
    do {                                                                      \
        float* ws_ = w_sA + (BUF) * 4608;                                     \
        float* xs_ = x_sA + (BUF) * 960;                                      \
        _Pragma("unroll")                                                     \
        for (int ii = 0; ii < 5; ++ii) {                                      \
            if (ii == 4 && !w4ok) break;                                      \
            const float* p_ = reinterpret_cast<const float*>(&wr[ii]);        \
            _Pragma("unroll")                                                 \
            for (int e = 0; e < 4; ++e) {                                     \
                int pk_ = wpk0[ii] + e;                                       \
                int s_  = (pk_ + (pk_ >> 2)) & 7;                             \
                ws_[(pk_ << 6) + ((woq[ii] ^ s_) << 3) + wsb[ii]] = p_[e];    \
            }                                                                 \
        }                                                                     \
        _Pragma("unroll")                                                     \
        for (int ii = 0; ii < 4; ++ii)                                        \
            if (xso[ii] >= 0) xs_[xso[ii]] = xr[ii];                          \
    } while (0)

    // ---- prologue: fill buf0, prefetch cc2=1 ----
    LOADS(0);
    STAGE(0);
    LOADS(1);

    // ---- pipelined main loop: ONE sync per iteration ----
    for (int cc2 = 0; cc2 < 16; ++cc2) {
        const int buf = cc2 & 1;
        __syncthreads();                       // buf ready; buf^1 readers done
        if (cc2 < 15) STAGE(buf ^ 1);          // stage cc2+1 from regs
        if (cc2 < 14) LOADS(cc2 + 2);          // issue gmem for cc2+2

        const float* ws = w_sA + buf * 4608;
        const float* xs = x_sA + buf * 960 + xrow;
#pragma unroll
        for (int k = 0; k < 9; ++k) {
            const int kh = k / 3, kw = k % 3;
            const float* xb = xs + ((kh * 10 + kw) << 5);
            ulonglong2 xa = *reinterpret_cast<const ulonglong2*>(xb);
            ulonglong2 xc = *reinterpret_cast<const ulonglong2*>(xb + 4);
            const float* wb = ws + woffk[k];
            ulonglong2 wa = *reinterpret_cast<const ulonglong2*>(wb);
            ulonglong2 wc = *reinterpret_cast<const ulonglong2*>(wb + 4);
            ull xs2[4] = {xa.x, xa.y, xc.x, xc.y};   // b = bg*4 + 0..3
            ull ws2[4] = {wa.x, wa.y, wc.x, wc.y};   // o = og*4 + 0..3
#pragma unroll
            for (int bi = 0; bi < 4; ++bi)
#pragma unroll
                for (int oi = 0; oi < 4; ++oi)
                    acc[bi][oi] = ffma2(xs2[bi], ws2[oi], acc[bi][oi]);
        }
    }

    // ---- epilogue: reduce c-pair, transpose via smem, coalesced STG ----
    __syncthreads();                           // all compute done; reuse smem
#pragma unroll
    for (int bi = 0; bi < 4; ++bi)
#pragma unroll
        for (int oi = 0; oi < 4; ++oi) {
            union { ull u; float2 f; } cv;
            cv.u = acc[bi][oi];
            int bo = (((bg << 2) + bi) << 5) + (og << 2) + oi;  // b*32 + o
            smem[bo * 10 + px] = cv.f.x + cv.f.y;
        }
    __syncthreads();
#pragma unroll
    for (int rr = 0; rr < 2; ++rr) {
        int r = tid + (rr << 8);               // r = b*32 + o
        const float* sp = smem + r * 10;
        float4 lo = make_float4(sp[0], sp[1], sp[2], sp[3]);
        float4 hi = make_float4(sp[4], sp[5], sp[6], sp[7]);
        float* op = out + (size_t)r * 4096 + pixbase;
        *reinterpret_cast<float4*>(op)     = lo;
        *reinterpret_cast<float4*>(op + 4) = hi;
    }
#undef LOADS
#undef STAGE
}

extern "C" void kernel_launch(void* const* d_in, const int* in_sizes, int n_in,
                              void* d_out, int out_size) {
    const float* x = (const float*)d_in[0];   // [16,32,64,64] f32
    const float* w = (const float*)d_in[1];   // [32,32,64,64,9] f32
    float* out = (float*)d_out;               // [16,32,64,64] f32
    dim3 grid(8, 64);
    lc2d_kernel<<<grid, 256>>>(x, w, out);
}

// round 6
// speedup vs baseline: 1.7992x; 1.2218x over previous
#include <cuda_runtime.h>

typedef unsigned long long ull;

__device__ __forceinline__ ull ffma2(ull a, ull b, ull c) {
    ull d;
    asm("fma.rn.f32x2 %0, %1, %2, %3;" : "=l"(d) : "l"(a), "l"(b), "l"(c));
    return d;
}

// LocallyConnected2d B=16,C=32,O=32,64x64,3x3,pad1. Block=8 px, 128 thr.
// Warp = 2 pixels (16 lanes each); thread tile 4b x 8o, f32x2 over (c,c+1).
//
// w smem: row pk(=pix*9+k) = 64 floats, zero pad. Slot og (16 floats =
// o in [og*8,og*8+8) x cc) split into 4 chunks of 16B; chunk j stored at
// granule (4j + og + 4*pix + (k&3)) & 15. Readers (4 og x 2 halves,
// bg-broadcast) hit 8 distinct granules -> 1 wavefront per LDS.128.
// x smem: pos*36 + b*2 + cc; reads also 8-granule broadcast.
// 2-deep pipeline, one syncthreads/iter. 45.5KB static smem.

#define W_BUF 4608
#define X_BUF 1080
#define X_BASE (2 * W_BUF)

__global__ __launch_bounds__(128, 2)
void lc2d_kernel(const float* __restrict__ xin,
                 const float* __restrict__ wgt,
                 float* __restrict__ out)
{
    __shared__ __align__(16) float smem[2 * W_BUF + 2 * X_BUF];  // 11376

    const int tid  = threadIdx.x;
    const int lane = tid & 31;
    const int pix  = (tid >> 5) * 2 + (lane >> 4);  // 0..7
    const int bg   = (lane >> 2) & 3;
    const int og   = lane & 3;

    const int oh      = blockIdx.y;
    const int ow0     = blockIdx.x << 3;
    const int pixbase = oh * 64 + ow0;

    // ---- compute-side per-k invariants ----
    int wrow[9], tk[9], xoff[9];
#pragma unroll
    for (int k = 0; k < 9; ++k) {
        int pk  = pix * 9 + k;
        wrow[k] = pk * 64;
        tk[k]   = og + pix * 4 + (k & 3);            // granule base (mod 16)
        xoff[k] = ((k / 3) * 10 + pix + (k % 3)) * 36 + bg * 8;
    }

    // ---- w staging invariants: 9 float4 slots/thread (1152 = 128*9) ----
    int wg[9], wst[9][4];
#pragma unroll
    for (int ii = 0; ii < 9; ++ii) {
        int f   = tid + ii * 128;
        int run = f / 18, v4 = f % 18;
        int o = run >> 1, cc = run & 1;
        wg[ii] = ((o * 32 + cc) * 4096 + pixbase) * 9 + v4 * 4;
        int idx16 = (o & 7) * 2 + cc;
        int chunk = idx16 >> 2, pos = idx16 & 3, slot = o >> 3;
#pragma unroll
        for (int e = 0; e < 4; ++e) {
            int pk = v4 * 4 + e;                     // 0..71
            int pr = pk / 9, kr = pk - pr * 9;
            int gran = (chunk * 4 + slot + pr * 4 + (kr & 3)) & 15;
            wst[ii][e] = pk * 64 + gran * 4 + pos;
        }
    }

    // ---- x staging invariants: 8 scalar slots (960 valid) ----
    int xg[8], xs_off[8];
#pragma unroll
    for (int ii = 0; ii < 8; ++ii) {
        int i = tid + ii * 128;
        xg[ii] = -1; xs_off[ii] = -1;
        if (i < 960) {
            int col = i % 10, r = i / 10;
            int row = r % 3, q = r / 3;
            int b = q >> 1, cc = q & 1;
            xs_off[ii] = (row * 10 + col) * 36 + b * 2 + cc;
            int ih = oh - 1 + row, iw = ow0 - 1 + col;
            if ((unsigned)ih < 64u && (unsigned)iw < 64u)
                xg[ii] = (b * 32 + cc) * 4096 + ih * 64 + iw;
        }
    }

    ull acc[4][8];
#pragma unroll
    for (int i = 0; i < 4; ++i)
#pragma unroll
        for (int j = 0; j < 8; ++j) acc[i][j] = 0ull;

    float4 wr[9];
    float  xr[8];

#define LOADS(CC2)                                                            \
    do {                                                                      \
        int c_ = (CC2) << 1;                                                  \
        _Pragma("unroll")                                                     \
        for (int ii = 0; ii < 9; ++ii)                                        \
            wr[ii] = *reinterpret_cast<const float4*>(wgt + wg[ii] + c_*36864);\
        _Pragma("unroll")                                                     \
        for (int ii = 0; ii < 8; ++ii)                                        \
            if (xs_off[ii] >= 0)                                              \
                xr[ii] = (xg[ii] >= 0) ? __ldg(xin + xg[ii] + c_ * 4096) : 0.f;\
    } while (0)

#define STAGE(BUF)                                                            \
    do {                                                                      \
        float* ws_ = smem + (BUF) * W_BUF;                                    \
        float* xs_ = smem + X_BASE + (BUF) * X_BUF;                           \
        _Pragma("unroll")                                                     \
        for (int ii = 0; ii < 9; ++ii) {                                      \
            ws_[wst[ii][0]] = wr[ii].x; ws_[wst[ii][1]] = wr[ii].y;           \
            ws_[wst[ii][2]] = wr[ii].z; ws_[wst[ii][3]] = wr[ii].w;           \
        }                                                                     \
        _Pragma("unroll")                                                     \
        for (int ii = 0; ii < 8; ++ii)                                        \
            if (xs_off[ii] >= 0) xs_[xs_off[ii]] = xr[ii];                    \
    } while (0)

    LOADS(0);
    STAGE(0);
    LOADS(1);

    for (int cc2 = 0; cc2 < 16; ++cc2) {
        const int buf = cc2 & 1;
        __syncthreads();                       // buf ready; buf^1 readers done
        if (cc2 < 15) STAGE(buf ^ 1);
        if (cc2 < 14) LOADS(cc2 + 2);

        const float* ws = smem + buf * W_BUF;
        const float* xs = smem + X_BASE + buf * X_BUF;
#pragma unroll
        for (int k = 0; k < 9; ++k) {
            const float* xb = xs + xoff[k];
            ulonglong2 x01 = *reinterpret_cast<const ulonglong2*>(xb);
            ulonglong2 x23 = *reinterpret_cast<const ulonglong2*>(xb + 4);
            ull xv[4] = {x01.x, x01.y, x23.x, x23.y};

            const float* wb = ws + wrow[k];
            const int t = tk[k];
            ulonglong2 w01 = *reinterpret_cast<const ulonglong2*>(wb + ((t     ) & 15) * 4);
            ulonglong2 w23 = *reinterpret_cast<const ulonglong2*>(wb + ((t +  4) & 15) * 4);
            ulonglong2 w45 = *reinterpret_cast<const ulonglong2*>(wb + ((t +  8) & 15) * 4);
            ulonglong2 w67 = *reinterpret_cast<const ulonglong2*>(wb + ((t + 12) & 15) * 4);
            ull wv[8] = {w01.x, w01.y, w23.x, w23.y,
                         w45.x, w45.y, w67.x, w67.y};
#pragma unroll
            for (int bi = 0; bi < 4; ++bi)
#pragma unroll
                for (int oi = 0; oi < 8; ++oi)
                    acc[bi][oi] = ffma2(xv[bi], wv[oi], acc[bi][oi]);
        }
    }

    // ---- epilogue: reduce c-pair, transpose via smem, 32B STG ----
    __syncthreads();
#pragma unroll
    for (int bi = 0; bi < 4; ++bi)
#pragma unroll
        for (int oi = 0; oi < 8; ++oi) {
            union { ull u; float2 f; } cv;
            cv.u = acc[bi][oi];
            int bo = (bg * 4 + bi) * 32 + og * 8 + oi;   // b*32 + o
            smem[bo * 10 + pix] = cv.f.x + cv.f.y;
        }
    __syncthreads();
#pragma unroll
    for (int rr = 0; rr < 4; ++rr) {
        int r = tid + rr * 128;                          // 0..511
        const float* sp = smem + r * 10;
        float4 lo = make_float4(sp[0], sp[1], sp[2], sp[3]);
        float4 hi = make_float4(sp[4], sp[5], sp[6], sp[7]);
        float* op = out + (size_t)r * 4096 + pixbase;
        *reinterpret_cast<float4*>(op)     = lo;
        *reinterpret_cast<float4*>(op + 4) = hi;
    }
#undef LOADS
#undef STAGE
}

extern "C" void kernel_launch(void* const* d_in, const int* in_sizes, int n_in,
                              void* d_out, int out_size) {
    const float* x = (const float*)d_in[0];   // [16,32,64,64] f32
    const float* w = (const float*)d_in[1];   // [32,32,64,64,9] f32
    float* out = (float*)d_out;               // [16,32,64,64] f32
    dim3 grid(8, 64);
    lc2d_kernel<<<grid, 128>>>(x, w, out);
}

// round 9
// speedup vs baseline: 2.2109x; 1.2289x over previous
// LocallyConnected2d (B=16, C=32, O=32, 64x64, k=3x3, pad=1) — sm_100a.
// Design: block = 8 horizontally adjacent pixels, 128 threads (4 warps).
// Warp covers 2 pixels (16 lanes each); per-thread tile 4b x 8o with
// fp32x2 packing over channel pairs (c even -> lo, c odd -> hi).
//
// Shared-memory weight layout: row pk = pix*9+k holds 64 floats.
// The 16-float group of o-slot `og` splits into four 16B chunks; chunk j
// lives at granule (4j + og + r(pk)) mod 16 where
//   r(pk) = (F0(pk mod 9) + 4*(pk div 9)) mod 8,  F0 = {0,1,2,3,4,5,6,7,3},
// and floats inside a granule rotate by 2*((pk div 9) & 1) (keeps cc pairs).
// Compute-side LDS.128: all 8 granule residues covered -> 1 wavefront.
// Staging STS: at most 2-way conflict (verified by enumeration).
// Readers compensate the intra-granule rotation via oi ^ (pix & 1).
// Two-stage software pipeline, one __syncthreads per c-pair iteration.

#include <cuda_runtime.h>

typedef unsigned long long u64t;

__device__ __forceinline__ u64t fma_f32x2(u64t a, u64t b, u64t c) {
    u64t d;
    asm("fma.rn.f32x2 %0, %1, %2, %3;" : "=l"(d) : "l"(a), "l"(b), "l"(c));
    return d;
}

#define WBUF_F 4608
#define XBUF_F 1080
#define XBASE_F (2 * WBUF_F)

__global__ __launch_bounds__(128, 2)
void lc2d_main(const float* __restrict__ xin,
               const float* __restrict__ wgt,
               float* __restrict__ out)
{
    __shared__ __align__(16) float sh[2 * WBUF_F + 2 * XBUF_F];  // 11376 f

    const int tid  = threadIdx.x;
    const int lane = tid & 31;
    const int og   = lane & 3;
    const int bg   = (lane >> 2) & 3;
    const int pix  = (tid >> 5) * 2 + (lane >> 4);   // 0..7
    const int swp  = pix & 1;

    const int oh      = blockIdx.y;
    const int ow0     = blockIdx.x << 3;
    const int pixbase = oh * 64 + ow0;

    // weight staging invariants: 9 float4 loads/thread; smem offsets packed
    int wgofs[9];
    unsigned wpack[18];
#pragma unroll
    for (int s = 0; s < 9; ++s) {
        int f   = tid + s * 128;
        int run = f / 18;
        int v4  = f - run * 18;
        int o   = run >> 1;
        int cc  = run & 1;
        wgofs[s] = ((o * 32 + cc) * 4096 + pixbase) * 9 + v4 * 4;
        int idx16 = (o & 7) * 2 + cc;
        int Cb    = (idx16 & ~3) + (o >> 3);
        int pos0  = idx16 & 3;
        int stv[4];
#pragma unroll
        for (int e = 0; e < 4; ++e) {
            int pk = v4 * 4 + e;                  // 0..71
            int p  = (pk * 57) >> 9;              // == pk / 9
            int q  = pk - p * 9;
            int f0 = q - 5 * (q >> 3);            // table {0..7,3}
            int rt = (f0 + 4 * p) & 7;
            stv[e] = pk * 64 + ((Cb + rt) & 15) * 4 + ((pos0 + 2 * (p & 1)) & 3);
        }
        wpack[s * 2]     = (unsigned)stv[0] | ((unsigned)stv[1] << 16);
        wpack[s * 2 + 1] = (unsigned)stv[2] | ((unsigned)stv[3] << 16);
    }

    // x staging invariants: slots 0..6 valid for all threads, slot 7 iff tid<64
    int xgofs[8];
    unsigned xpack[4];
#pragma unroll
    for (int s = 0; s < 8; ++s) {
        int i  = tid + s * 128;
        int so = 0;
        xgofs[s] = -1;
        if (i < 960) {
            int col = i % 10;
            int r   = i / 10;
            int row = r % 3;
            int qb  = r / 3;
            int b   = qb >> 1;
            int cc  = qb & 1;
            so = (row * 10 + col) * 36 + b * 2 + cc;
            int ih = oh - 1 + row;
            int iw = ow0 - 1 + col;
            if ((unsigned)ih < 64u && (unsigned)iw < 64u)
                xgofs[s] = (b * 32 + cc) * 4096 + ih * 64 + iw;
        }
        if (s & 1) xpack[s >> 1] |= (unsigned)so << 16;
        else       xpack[s >> 1]  = (unsigned)so;
    }
    const bool has7 = (tid < 64);

    const int wreadb = pix * 576;                 // (pix*9) * 64
    const int xreadb = pix * 36 + bg * 8;

    u64t acc[4][8];
#pragma unroll
    for (int i = 0; i < 4; ++i)
#pragma unroll
        for (int j = 0; j < 8; ++j) acc[i][j] = 0ull;

    float4 wreg[9];
    float  xreg[8];

#define DO_LOADS(CC2)                                                         \
    do {                                                                      \
        int cl = (CC2) << 1;                                                  \
        _Pragma("unroll")                                                     \
        for (int s = 0; s < 9; ++s)                                           \
            wreg[s] = *reinterpret_cast<const float4*>(                       \
                wgt + wgofs[s] + cl * 36864);                                 \
        _Pragma("unroll")                                                     \
        for (int s = 0; s < 7; ++s)                                           \
            xreg[s] = (xgofs[s] >= 0) ? __ldg(xin + xgofs[s] + cl * 4096)     \
                                      : 0.f;                                  \
        if (has7)                                                             \
            xreg[7] = (xgofs[7] >= 0) ? __ldg(xin + xgofs[7] + cl * 4096)     \
                                      : 0.f;                                  \
    } while (0)

#define DO_STAGE(BUF)                                                         \
    do {                                                                      \
        float* wd = sh + (BUF) * WBUF_F;                                      \
        float* xd = sh + XBASE_F + (BUF) * XBUF_F;                            \
        _Pragma("unroll")                                                     \
        for (int s = 0; s < 9; ++s) {                                         \
            wd[wpack[2*s] & 0xffffu]   = wreg[s].x;                           \
            wd[wpack[2*s] >> 16]       = wreg[s].y;                           \
            wd[wpack[2*s+1] & 0xffffu] = wreg[s].z;                           \
            wd[wpack[2*s+1] >> 16]     = wreg[s].w;                           \
        }                                                                     \
        _Pragma("unroll")                                                     \
        for (int s = 0; s < 7; ++s)                                           \
            xd[(xpack[s>>1] >> ((s&1)*16)) & 0xffffu] = xreg[s];              \
        if (has7) xd[xpack[3] >> 16] = xreg[7];                               \
    } while (0)

    DO_LOADS(0);
    DO_STAGE(0);
    DO_LOADS(1);

    for (int cc2 = 0; cc2 < 16; ++cc2) {
        const int buf = cc2 & 1;
        __syncthreads();                    // buf filled; buf^1 fully consumed
        if (cc2 < 15) DO_STAGE(buf ^ 1);
        if (cc2 < 14) DO_LOADS(cc2 + 2);

        const float* wp = sh + buf * WBUF_F + wreadb;
        const float* xp = sh + XBASE_F + buf * XBUF_F + xreadb;
#pragma unroll
        for (int k = 0; k < 9; ++k) {
            const int f0k = (k < 8) ? k : 3;
            const float* xb = xp + ((k / 3) * 10 + (k % 3)) * 36;
            ulonglong2 xlo = *reinterpret_cast<const ulonglong2*>(xb);
            ulonglong2 xhi = *reinterpret_cast<const ulonglong2*>(xb + 4);
            u64t xv[4] = {xlo.x, xlo.y, xhi.x, xhi.y};

            const float* wb = wp + k * 64;
            const int t = og + ((f0k + 4 * pix) & 7);
            ulonglong2 wa = *reinterpret_cast<const ulonglong2*>(wb + ((t     ) & 15) * 4);
            ulonglong2 wbv= *reinterpret_cast<const ulonglong2*>(wb + ((t +  4) & 15) * 4);
            ulonglong2 wc = *reinterpret_cast<const ulonglong2*>(wb + ((t +  8) & 15) * 4);
            ulonglong2 wd = *reinterpret_cast<const ulonglong2*>(wb + ((t + 12) & 15) * 4);
            u64t wv[8] = {wa.x, wa.y, wbv.x, wbv.y, wc.x, wc.y, wd.x, wd.y};
#pragma unroll
            for (int bi = 0; bi < 4; ++bi)
#pragma unroll
                for (int oi = 0; oi < 8; ++oi)
                    acc[bi][oi] = fma_f32x2(xv[bi], wv[oi], acc[bi][oi]);
        }
    }

    // epilogue: sum cc pair, undo rotation swap, transpose via smem, 32B STG
    __syncthreads();
#pragma unroll
    for (int bi = 0; bi < 4; ++bi)
#pragma unroll
        for (int oi = 0; oi < 8; ++oi) {
            union { u64t u; float2 f; } cv;
            cv.u = acc[bi][oi];
            int bo = (bg * 4 + bi) * 32 + og * 8 + (oi ^ swp);
            sh[bo * 10 + pix] = cv.f.x + cv.f.y;
        }
    __syncthreads();
#pragma unroll
    for (int rr = 0; rr < 4; ++rr) {
        int r = tid + rr * 128;             // r = b*32 + o
        const float* sp = sh + r * 10;
        float4 lo = make_float4(sp[0], sp[1], sp[2], sp[3]);
        float4 hi = make_float4(sp[4], sp[5], sp[6], sp[7]);
        float* op = out + (size_t)r * 4096 + pixbase;
        *reinterpret_cast<float4*>(op)     = lo;
        *reinterpret_cast<float4*>(op + 4) = hi;
    }
#undef DO_LOADS
#undef DO_STAGE
}

extern "C" void kernel_launch(void* const* d_in, const int* in_sizes, int n_in,
                              void* d_out, int out_size) {
    const float* x = (const float*)d_in[0];   // [16,32,64,64] float32
    const float* w = (const float*)d_in[1];   // [32,32,64,64,9] float32
    float* y = (float*)d_out;                 // [16,32,64,64] float32
    dim3 grid(8, 64);
    lc2d_main<<<grid, 128>>>(x, w, y);
}